// round 10
// baseline (speedup 1.0000x reference)
#include <cuda_runtime.h>
#include <cuda_fp16.h>

#define NN 100000
#define NE 1280000
#define FD 64
#define NG 1000
#define BN_EPS 1e-5f
#define SCAN_CH 1024
#define SCAN_NB ((NN + SCAN_CH - 1) / SCAN_CH)   // 98

// ---------------- device scratch (allocation-free rule: __device__ globals) ----
__device__ int    g_deg[NN];
__device__ float  g_dinv[NN];
__device__ __half g_th[(size_t)NN * FD];      // transformed features (fp16 messages)
__device__ float  g_agg[(size_t)NN * FD];     // aggregated features (fp32)
__device__ float  g_stats[6 * FD];            // s1 ss1 | s2 ss2 | s3 ss3
__device__ float  g_gsum[NG * FD];
__device__ float  g_gcnt[NG];
__device__ int    g_is64;
// CSR sorted by destination; packed (src, norm-bits)
__device__ int    g_rowptr[NN + 1];
__device__ int    g_fill[NN];
__device__ int2   g_csr[NE];
// decoupled-lookback scan state (reset by init each launch)
__device__ volatile int g_scan_status[SCAN_NB];   // 0=invalid 1=agg 2=prefix
__device__ int    g_scan_agg[SCAN_NB];
__device__ int    g_scan_pref[SCAN_NB];

__device__ __forceinline__ unsigned pack_half2(float a, float b) {
    __half2 h = __floats2half2_rn(a, b);
    return (unsigned)__half_as_ushort(__low2half(h)) |
           ((unsigned)__half_as_ushort(__high2half(h)) << 16);
}

// ---------------- init + dtype detect (block 0 detects int64 via odd words==0)
__global__ void init_kernel(const int* __restrict__ ei) {
    int i = blockIdx.x * blockDim.x + threadIdx.x;
    if (i < NN) g_deg[i] = 0;
    if (i < 6 * FD) g_stats[i] = 0.0f;
    if (i < NG * FD) g_gsum[i] = 0.0f;
    if (i < NG) g_gcnt[i] = 0.0f;
    if (i < SCAN_NB) g_scan_status[i] = 0;
    if (blockIdx.x == 0) {
        __shared__ int nz;
        if (threadIdx.x == 0) nz = 0;
        __syncthreads();
        int local = 0;
        for (int k = threadIdx.x; k < 4096; k += blockDim.x)
            if (ei[2 * k + 1] != 0) local = 1;
        if (local) nz = 1;
        __syncthreads();
        if (threadIdx.x == 0) g_is64 = (nz == 0) ? 1 : 0;
    }
}

// ---------------- degree: 2 edges per thread, vectorized index loads --------
__global__ void deg_kernel(const int* __restrict__ ei) {
    int e2 = blockIdx.x * blockDim.x + threadIdx.x;    // edge pair id
    if (e2 >= NE / 2) return;
    int c0, c1;
    if (g_is64) {
        int4 p = ((const int4*)(ei + 2 * NE))[e2];     // col[2e],col[2e+1] as int64
        c0 = p.x; c1 = p.z;
    } else {
        int2 p = ((const int2*)(ei + NE))[e2];
        c0 = p.x; c1 = p.y;
    }
    atomicAdd(&g_deg[c0], 1);
    atomicAdd(&g_deg[c1], 1);
}

// ---------------- fused: rsqrt(deg+1) + single-pass exclusive scan ----------
// Decoupled lookback; 98 blocks (all resident on 148 SMs -> no deadlock).
__global__ void scan_kernel() {
    __shared__ int sh[257];
    __shared__ int sExc;
    int b = blockIdx.x, t = threadIdx.x;
    int base = b * SCAN_CH + t * 4;
    int v[4]; int s = 0;
#pragma unroll
    for (int k = 0; k < 4; k++) {
        int i = base + k;
        v[k] = (i < NN) ? g_deg[i] : 0;
        if (i < NN) g_dinv[i] = rsqrtf((float)v[k] + 1.0f);
        s += v[k];
    }
    sh[t + 1] = s;
    if (t == 0) sh[0] = 0;
    __syncthreads();
    // inclusive scan over sh[1..256]
    for (int off = 1; off < 256; off <<= 1) {
        int val = (t + 1 > off) ? sh[t + 1 - off] : 0;
        __syncthreads();
        sh[t + 1] += val;
        __syncthreads();
    }
    int total = sh[256];

    // publish aggregate / prefix, lookback for exclusive offset
    if (t == 0) {
        if (b == 0) {
            g_scan_pref[0] = total;
            __threadfence();
            g_scan_status[0] = 2;
            sExc = 0;
        } else {
            g_scan_agg[b] = total;
            __threadfence();
            g_scan_status[b] = 1;
            int exc = 0;
            int j = b - 1;
            while (true) {
                int st;
                do { st = g_scan_status[j]; } while (st == 0);
                __threadfence();
                if (st == 2) { exc += g_scan_pref[j]; break; }
                exc += g_scan_agg[j];
                j--;
            }
            g_scan_pref[b] = exc + total;
            __threadfence();
            g_scan_status[b] = 2;
            sExc = exc;
        }
        if (b == SCAN_NB - 1) g_rowptr[NN] = g_scan_pref[b];  // == NE
    }
    __syncthreads();
    int run = sExc + sh[t];
#pragma unroll
    for (int k = 0; k < 4; k++) {
        int i = base + k;
        if (i < NN) { g_rowptr[i] = run; g_fill[i] = run; run += v[k]; }
    }
}

// ---------------- edge placement into CSR: 2 edges/thread, vector loads -----
__global__ void place_kernel(const int* __restrict__ ei) {
    int e2 = blockIdx.x * blockDim.x + threadIdx.x;
    if (e2 >= NE / 2) return;
    int r0, c0, r1, c1;
    if (g_is64) {
        int4 pr = ((const int4*)ei)[e2];
        int4 pc = ((const int4*)(ei + 2 * NE))[e2];
        r0 = pr.x; r1 = pr.z; c0 = pc.x; c1 = pc.z;
    } else {
        int2 pr = ((const int2*)ei)[e2];
        int2 pc = ((const int2*)(ei + NE))[e2];
        r0 = pr.x; r1 = pr.y; c0 = pc.x; c1 = pc.y;
    }
    float d0 = g_dinv[r0], dc0 = g_dinv[c0];
    float d1 = g_dinv[r1], dc1 = g_dinv[c1];
    int pos0 = atomicAdd(&g_fill[c0], 1);
    g_csr[pos0] = make_int2(r0, __float_as_int(d0 * dc0));
    int pos1 = atomicAdd(&g_fill[c1], 1);
    g_csr[pos1] = make_int2(r1, __float_as_int(d1 * dc1));
}

// ---------------- BN stats for layer-1 input x ------------------------------
__global__ void bn_stats_x_kernel(const float* __restrict__ x) {
    int f   = threadIdx.x & 63;
    int sub = threadIdx.x >> 6;
    float s = 0.0f, ss = 0.0f;
    for (int n = blockIdx.x * 4 + sub; n < NN; n += gridDim.x * 4) {
        float v = x[(size_t)n * FD + f];
        s += v; ss += v * v;
    }
    atomicAdd(&g_stats[f], s);
    atomicAdd(&g_stats[64 + f], ss);
}

// ---------------- GEMM with fused BN fold:  t = prologue(in) @ (diag(a)W) + c@W
// prologue = relu(in + bias) if dorelu.  Output fp16.
// 64 rows/block, 256 threads, 4x4 register blocking (best-measured variant).
__global__ void gemm_kernel(const float* __restrict__ xin, int use_agg,
                            const float* __restrict__ bias, int dorelu,
                            const float* __restrict__ gg, const float* __restrict__ bb,
                            const float* __restrict__ W, int soff) {
    __shared__ float sIn[64 * 68];          // pad 68: float4-aligned rows, conflict-free
    __shared__ float sW[FD * FD];
    __shared__ float sA[FD], sC[FD], sCrow[FD];
    const float* __restrict__ src = use_agg ? g_agg : xin;
    int tid = threadIdx.x;

    // raw W into smem + BN fold coefficients
    for (int i = tid; i < FD * FD; i += 256) sW[i] = W[i];
    if (tid < FD) {
        float m = g_stats[soff + tid] * (1.0f / NN);
        float v = fmaxf(g_stats[soff + 64 + tid] * (1.0f / NN) - m * m, 0.0f);
        float af = gg[tid] * rsqrtf(v + BN_EPS);
        sA[tid] = af;
        sC[tid] = bb[tid] - m * af;
    }
    __syncthreads();

    // input tile load (overlapped with crow compute below)
    int base = blockIdx.x * 64;
    int nrows = min(64, NN - base);
    for (int i = tid; i < 64 * 16; i += 256) {
        int r = i >> 4, kc = i & 15;
        float4 v = make_float4(0.f, 0.f, 0.f, 0.f);
        if (r < nrows) {
            v = ((const float4*)src)[(size_t)(base + r) * 16 + kc];
            if (dorelu) {
                float4 bv = ((const float4*)bias)[kc];
                v.x = fmaxf(v.x + bv.x, 0.0f);
                v.y = fmaxf(v.y + bv.y, 0.0f);
                v.z = fmaxf(v.z + bv.z, 0.0f);
                v.w = fmaxf(v.w + bv.w, 0.0f);
            }
        }
        *((float4*)&sIn[r * 68 + kc * 4]) = v;
    }
    float cr = 0.0f;
    if (tid < FD) {
        for (int i = 0; i < FD; i++) cr += sC[i] * sW[i * FD + tid];
    }
    __syncthreads();

    // scale sW in place, publish crow
    for (int i = tid; i < FD * FD; i += 256) sW[i] *= sA[i >> 6];
    if (tid < FD) sCrow[tid] = cr;
    __syncthreads();

    int rp = tid >> 4, tc = tid & 15;      // rp: 4-row group, tc: 4-col group
    int rbase = rp * 4;
    float4 acc0 = make_float4(0.f, 0.f, 0.f, 0.f);
    float4 acc1 = make_float4(0.f, 0.f, 0.f, 0.f);
    float4 acc2 = make_float4(0.f, 0.f, 0.f, 0.f);
    float4 acc3 = make_float4(0.f, 0.f, 0.f, 0.f);
    const float4* sW4 = (const float4*)sW;
#pragma unroll
    for (int k = 0; k < FD; k++) {
        float4 w = sW4[k * 16 + tc];
        float x0 = sIn[(rbase + 0) * 68 + k];
        float x1 = sIn[(rbase + 1) * 68 + k];
        float x2 = sIn[(rbase + 2) * 68 + k];
        float x3 = sIn[(rbase + 3) * 68 + k];
        acc0.x += x0 * w.x; acc0.y += x0 * w.y; acc0.z += x0 * w.z; acc0.w += x0 * w.w;
        acc1.x += x1 * w.x; acc1.y += x1 * w.y; acc1.z += x1 * w.z; acc1.w += x1 * w.w;
        acc2.x += x2 * w.x; acc2.y += x2 * w.y; acc2.z += x2 * w.z; acc2.w += x2 * w.w;
        acc3.x += x3 * w.x; acc3.y += x3 * w.y; acc3.z += x3 * w.z; acc3.w += x3 * w.w;
    }
    float4 crw = ((const float4*)sCrow)[tc];
    acc0.x += crw.x; acc0.y += crw.y; acc0.z += crw.z; acc0.w += crw.w;
    acc1.x += crw.x; acc1.y += crw.y; acc1.z += crw.z; acc1.w += crw.w;
    acc2.x += crw.x; acc2.y += crw.y; acc2.z += crw.z; acc2.w += crw.w;
    acc3.x += crw.x; acc3.y += crw.y; acc3.z += crw.z; acc3.w += crw.w;

    uint2* th2 = (uint2*)g_th;
    if (rbase + 0 < nrows) th2[(size_t)(base + rbase + 0) * 16 + tc] = make_uint2(pack_half2(acc0.x, acc0.y), pack_half2(acc0.z, acc0.w));
    if (rbase + 1 < nrows) th2[(size_t)(base + rbase + 1) * 16 + tc] = make_uint2(pack_half2(acc1.x, acc1.y), pack_half2(acc1.z, acc1.w));
    if (rbase + 2 < nrows) th2[(size_t)(base + rbase + 2) * 16 + tc] = make_uint2(pack_half2(acc2.x, acc2.y), pack_half2(acc2.z, acc2.w));
    if (rbase + 3 < nrows) th2[(size_t)(base + rbase + 3) * 16 + tc] = make_uint2(pack_half2(acc3.x, acc3.y), pack_half2(acc3.z, acc3.w));
}

// ---------------- CSR gather conv: warp/node, lane = 2 feats, fp16 messages.
// Optional epilogue: BN stats of relu(agg + bias) via block reduction.
__global__ void gather_kernel(int do_stats, const float* __restrict__ bias, int soff) {
    __shared__ float sStat[128];
    int tid  = threadIdx.x;
    int lane = tid & 31;
    if (do_stats && tid < 128) sStat[tid] = 0.0f;

    int n = (blockIdx.x * blockDim.x + tid) >> 5;   // 16 nodes per 512-thread block
    const __half2* th2 = (const __half2*)g_th;
    float d = g_dinv[n];
    float s = d * d;
    float2 acc = __half22float2(th2[(size_t)n * 32 + lane]);
    acc.x *= s; acc.y *= s;

    int j = g_rowptr[n], end = g_rowptr[n + 1];
    for (; j + 2 <= end; j += 2) {
        int2 p0 = g_csr[j];
        int2 p1 = g_csr[j + 1];
        float2 v0 = __half22float2(th2[(size_t)p0.x * 32 + lane]);
        float2 v1 = __half22float2(th2[(size_t)p1.x * 32 + lane]);
        float w0 = __int_as_float(p0.y), w1 = __int_as_float(p1.y);
        acc.x += v0.x * w0 + v1.x * w1;
        acc.y += v0.y * w0 + v1.y * w1;
    }
    if (j < end) {
        int2 p = g_csr[j];
        float2 v = __half22float2(th2[(size_t)p.x * 32 + lane]);
        float w = __int_as_float(p.y);
        acc.x += v.x * w;
        acc.y += v.y * w;
    }
    ((float2*)g_agg)[(size_t)n * 32 + lane] = acc;

    if (do_stats) {
        float2 bb = ((const float2*)bias)[lane];
        float y0 = fmaxf(acc.x + bb.x, 0.0f);
        float y1 = fmaxf(acc.y + bb.y, 0.0f);
        __syncthreads();             // zero-fill visible, all accs done
        atomicAdd(&sStat[2 * lane],      y0);
        atomicAdd(&sStat[2 * lane + 1],  y1);
        atomicAdd(&sStat[64 + 2 * lane],     y0 * y0);
        atomicAdd(&sStat[64 + 2 * lane + 1], y1 * y1);
        __syncthreads();
        if (tid < 128) atomicAdd(&g_stats[soff + tid], sStat[tid]);
    }
}

// ---------------- pool: y=relu(agg+b2); BN3 stats + per-graph sums (batch sorted)
__global__ void pool_kernel(const float* __restrict__ bias, const int* __restrict__ batch) {
    int f   = threadIdx.x & 63;
    int sub = threadIdx.x >> 6;
    int is64 = g_is64;
    float bs = bias[f];
    const int chunk = 196;                 // 512 blocks * 196 >= NN
    const int subc  = 49;
    int start = blockIdx.x * chunk + sub * subc;
    int stop  = min(start + subc, NN);
    float s = 0.0f, ss = 0.0f;
    int   cur = -1;
    float gv = 0.0f, gc = 0.0f;
    for (int n = start; n < stop; n++) {
        int b = is64 ? batch[2 * n] : batch[n];
        if (b != cur) {
            if (cur >= 0) {
                atomicAdd(&g_gsum[cur * FD + f], gv);
                if (f == 0) atomicAdd(&g_gcnt[cur], gc);
            }
            cur = b; gv = 0.0f; gc = 0.0f;
        }
        float v = fmaxf(g_agg[(size_t)n * FD + f] + bs, 0.0f);
        s += v; ss += v * v;
        gv += v; gc += 1.0f;
    }
    if (cur >= 0) {
        atomicAdd(&g_gsum[cur * FD + f], gv);
        if (f == 0) atomicAdd(&g_gcnt[cur], gc);
    }
    atomicAdd(&g_stats[256 + f], s);
    atomicAdd(&g_stats[320 + f], ss);
}

// ---------------- final: fold BN3 into Wout, emit [NG, 2] --------------------
__global__ void final_kernel(const float* __restrict__ gg, const float* __restrict__ bb,
                             const float* __restrict__ Wout, const float* __restrict__ bout,
                             float* __restrict__ out) {
    __shared__ float sWp[FD * 2];
    __shared__ float sc[FD];
    __shared__ float scb[2];
    int tid = threadIdx.x;
    if (tid < FD) {
        float m = g_stats[256 + tid] * (1.0f / NN);
        float v = fmaxf(g_stats[320 + tid] * (1.0f / NN) - m * m, 0.0f);
        float af = gg[tid] * rsqrtf(v + BN_EPS);
        sc[tid] = bb[tid] - m * af;
        sWp[tid * 2]     = af * Wout[tid * 2];
        sWp[tid * 2 + 1] = af * Wout[tid * 2 + 1];
    }
    __syncthreads();
    if (tid < 2) {
        float acc = bout[tid];
        for (int i = 0; i < FD; i++) acc += sc[i] * Wout[i * 2 + tid];
        scb[tid] = acc;
    }
    __syncthreads();
    int g = blockIdx.x * blockDim.x + tid;
    if (g >= NG) return;
    float cnt = g_gcnt[g];
    if (cnt > 0.0f) {
        float inv = 1.0f / cnt;
        float a0 = scb[0], a1 = scb[1];
#pragma unroll 8
        for (int f = 0; f < FD; f++) {
            float p = g_gsum[g * FD + f] * inv;
            a0 += p * sWp[f * 2];
            a1 += p * sWp[f * 2 + 1];
        }
        out[g * 2] = a0; out[g * 2 + 1] = a1;
    } else {
        out[g * 2] = bout[0]; out[g * 2 + 1] = bout[1];
    }
}

extern "C" void kernel_launch(void* const* d_in, const int* in_sizes, int n_in,
                              void* d_out, int out_size) {
    const float* x       = (const float*)d_in[0];
    const int*   ei      = (const int*)d_in[1];
    const int*   batch   = (const int*)d_in[2];
    const float* bn_in_g = (const float*)d_in[3];
    const float* bn_in_b = (const float*)d_in[4];
    const float* W1      = (const float*)d_in[5];
    const float* b1      = (const float*)d_in[6];
    const float* g1      = (const float*)d_in[7];
    const float* be1     = (const float*)d_in[8];
    const float* W2      = (const float*)d_in[9];
    const float* b2      = (const float*)d_in[10];
    const float* g2      = (const float*)d_in[11];
    const float* be2     = (const float*)d_in[12];
    const float* Wout    = (const float*)d_in[13];
    const float* bout    = (const float*)d_in[14];
    float* out = (float*)d_out;

    const int GEMM_GRID = (NN + 63) / 64;   // 1563

    init_kernel<<<(NN + 255) / 256, 256>>>(ei);                           // 1
    deg_kernel<<<(NE / 2 + 255) / 256, 256>>>(ei);                        // 2
    scan_kernel<<<SCAN_NB, 256>>>();                                      // 3 (fused rsqrt+scan)
    place_kernel<<<(NE / 2 + 255) / 256, 256>>>(ei);                      // 4  <- profiled
    bn_stats_x_kernel<<<512, 256>>>(x);                                   // 5
    gemm_kernel<<<GEMM_GRID, 256>>>(x, 0, x, 0, bn_in_g, bn_in_b, W1, 0); // 6
    gather_kernel<<<NN / 16, 512>>>(1, b1, 128);                          // 7
    gemm_kernel<<<GEMM_GRID, 256>>>(x, 1, b1, 1, g1, be1, W2, 128);       // 8
    gather_kernel<<<NN / 16, 512>>>(0, b1, 0);                            // 9
    pool_kernel<<<512, 256>>>(b2, batch);                                 // 10
    final_kernel<<<4, 256>>>(g2, be2, Wout, bout, out);                   // 11
}

// round 11
// speedup vs baseline: 1.0062x; 1.0062x over previous
#include <cuda_runtime.h>
#include <cuda_fp16.h>

#define NN 100000
#define NE 1280000
#define FD 64
#define NG 1000
#define BN_EPS 1e-5f
#define SCAN_CH 1024
#define SCAN_NB ((NN + SCAN_CH - 1) / SCAN_CH)   // 98

// ---------------- device scratch (allocation-free rule: __device__ globals) ----
__device__ int    g_deg[NN];
__device__ float  g_dinv[NN];
__device__ __half g_th[(size_t)NN * FD];      // dinv-scaled messages (fp16)
__device__ float  g_agg[(size_t)NN * FD];     // aggregated features (fp32)
__device__ float  g_stats[6 * FD];            // s1 ss1 | s2 ss2 | s3 ss3
__device__ float  g_gsum[NG * FD];
__device__ float  g_gcnt[NG];
__device__ int    g_is64;
// CSR sorted by destination: src index only (norm factored into messages)
__device__ int    g_rowptr[NN + 1];
__device__ int    g_fill[NN];
__device__ int    g_csr_src[NE];
// decoupled-lookback scan state (reset by init each launch)
__device__ volatile int g_scan_status[SCAN_NB];   // 0=invalid 1=agg 2=prefix
__device__ volatile int g_scan_agg[SCAN_NB];
__device__ volatile int g_scan_pref[SCAN_NB];

__device__ __forceinline__ unsigned pack_half2(float a, float b) {
    __half2 h = __floats2half2_rn(a, b);
    return (unsigned)__half_as_ushort(__low2half(h)) |
           ((unsigned)__half_as_ushort(__high2half(h)) << 16);
}

// ---------------- init + dtype detect (block 0 detects int64 via odd words==0)
__global__ void init_kernel(const int* __restrict__ ei) {
    int i = blockIdx.x * blockDim.x + threadIdx.x;
    if (i < NN) g_deg[i] = 0;
    if (i < 6 * FD) g_stats[i] = 0.0f;
    if (i < NG * FD) g_gsum[i] = 0.0f;
    if (i < NG) g_gcnt[i] = 0.0f;
    if (i < SCAN_NB) g_scan_status[i] = 0;
    if (blockIdx.x == 0) {
        __shared__ int nz;
        if (threadIdx.x == 0) nz = 0;
        __syncthreads();
        int local = 0;
        for (int k = threadIdx.x; k < 4096; k += blockDim.x)
            if (ei[2 * k + 1] != 0) local = 1;
        if (local) nz = 1;
        __syncthreads();
        if (threadIdx.x == 0) g_is64 = (nz == 0) ? 1 : 0;
    }
}

// ---------------- degree: 2 edges per thread, vectorized index loads --------
__global__ void deg_kernel(const int* __restrict__ ei) {
    int e2 = blockIdx.x * blockDim.x + threadIdx.x;    // edge pair id
    if (e2 >= NE / 2) return;
    int c0, c1;
    if (g_is64) {
        int4 p = ((const int4*)(ei + 2 * NE))[e2];
        c0 = p.x; c1 = p.z;
    } else {
        int2 p = ((const int2*)(ei + NE))[e2];
        c0 = p.x; c1 = p.y;
    }
    atomicAdd(&g_deg[c0], 1);
    atomicAdd(&g_deg[c1], 1);
}

// ---------------- fused: rsqrt(deg+1) + single-pass exclusive scan ----------
__global__ void scan_kernel() {
    __shared__ int sh[257];
    __shared__ int sExc;
    int b = blockIdx.x, t = threadIdx.x;
    int base = b * SCAN_CH + t * 4;
    int v[4]; int s = 0;
#pragma unroll
    for (int k = 0; k < 4; k++) {
        int i = base + k;
        v[k] = (i < NN) ? g_deg[i] : 0;
        if (i < NN) g_dinv[i] = rsqrtf((float)v[k] + 1.0f);
        s += v[k];
    }
    sh[t + 1] = s;
    if (t == 0) sh[0] = 0;
    __syncthreads();
    for (int off = 1; off < 256; off <<= 1) {
        int val = (t + 1 > off) ? sh[t + 1 - off] : 0;
        __syncthreads();
        sh[t + 1] += val;
        __syncthreads();
    }
    int total = sh[256];

    if (t == 0) {
        if (b == 0) {
            g_scan_pref[0] = total;
            __threadfence();
            g_scan_status[0] = 2;
            sExc = 0;
        } else {
            g_scan_agg[b] = total;
            __threadfence();
            g_scan_status[b] = 1;
            int exc = 0;
            int j = b - 1;
            while (true) {
                int st;
                do { st = g_scan_status[j]; } while (st == 0);
                __threadfence();
                if (st == 2) { exc += g_scan_pref[j]; break; }
                exc += g_scan_agg[j];
                j--;
            }
            g_scan_pref[b] = exc + total;
            __threadfence();
            g_scan_status[b] = 2;
            sExc = exc;
        }
        if (b == SCAN_NB - 1) g_rowptr[NN] = g_scan_pref[b];  // == NE
    }
    __syncthreads();
    int run = sExc + sh[t];
#pragma unroll
    for (int k = 0; k < 4; k++) {
        int i = base + k;
        if (i < NN) { g_rowptr[i] = run; g_fill[i] = run; run += v[k]; }
    }
}

// ---------------- edge placement into CSR: src only (4B scattered writes) ---
__global__ void place_kernel(const int* __restrict__ ei) {
    int e2 = blockIdx.x * blockDim.x + threadIdx.x;
    if (e2 >= NE / 2) return;
    int r0, c0, r1, c1;
    if (g_is64) {
        int4 pr = ((const int4*)ei)[e2];
        int4 pc = ((const int4*)(ei + 2 * NE))[e2];
        r0 = pr.x; r1 = pr.z; c0 = pc.x; c1 = pc.z;
    } else {
        int2 pr = ((const int2*)ei)[e2];
        int2 pc = ((const int2*)(ei + NE))[e2];
        r0 = pr.x; r1 = pr.y; c0 = pc.x; c1 = pc.y;
    }
    int pos0 = atomicAdd(&g_fill[c0], 1);
    g_csr_src[pos0] = r0;
    int pos1 = atomicAdd(&g_fill[c1], 1);
    g_csr_src[pos1] = r1;
}

// ---------------- BN stats for layer-1 input x ------------------------------
__global__ void bn_stats_x_kernel(const float* __restrict__ x) {
    int f   = threadIdx.x & 63;
    int sub = threadIdx.x >> 6;
    float s = 0.0f, ss = 0.0f;
    for (int n = blockIdx.x * 4 + sub; n < NN; n += gridDim.x * 4) {
        float v = x[(size_t)n * FD + f];
        s += v; ss += v * v;
    }
    atomicAdd(&g_stats[f], s);
    atomicAdd(&g_stats[64 + f], ss);
}

// ---------------- GEMM with fused BN fold + dinv scale ----------------------
//   th = dinv[n] * ( prologue(in) @ (diag(a)W) + c@W )
// prologue = relu(in + bias) if dorelu.  Output fp16, 64 rows/block.
__global__ void gemm_kernel(const float* __restrict__ xin, int use_agg,
                            const float* __restrict__ bias, int dorelu,
                            const float* __restrict__ gg, const float* __restrict__ bb,
                            const float* __restrict__ W, int soff) {
    __shared__ float sIn[64 * 68];          // pad 68: float4-aligned rows, conflict-free
    __shared__ float sW[FD * FD];
    __shared__ float sA[FD], sC[FD], sCrow[FD];
    const float* __restrict__ src = use_agg ? g_agg : xin;
    int tid = threadIdx.x;

    for (int i = tid; i < FD * FD; i += 256) sW[i] = W[i];
    if (tid < FD) {
        float m = g_stats[soff + tid] * (1.0f / NN);
        float v = fmaxf(g_stats[soff + 64 + tid] * (1.0f / NN) - m * m, 0.0f);
        float af = gg[tid] * rsqrtf(v + BN_EPS);
        sA[tid] = af;
        sC[tid] = bb[tid] - m * af;
    }
    __syncthreads();

    int base = blockIdx.x * 64;
    int nrows = min(64, NN - base);
    for (int i = tid; i < 64 * 16; i += 256) {
        int r = i >> 4, kc = i & 15;
        float4 v = make_float4(0.f, 0.f, 0.f, 0.f);
        if (r < nrows) {
            v = ((const float4*)src)[(size_t)(base + r) * 16 + kc];
            if (dorelu) {
                float4 bv = ((const float4*)bias)[kc];
                v.x = fmaxf(v.x + bv.x, 0.0f);
                v.y = fmaxf(v.y + bv.y, 0.0f);
                v.z = fmaxf(v.z + bv.z, 0.0f);
                v.w = fmaxf(v.w + bv.w, 0.0f);
            }
        }
        *((float4*)&sIn[r * 68 + kc * 4]) = v;
    }
    float cr = 0.0f;
    if (tid < FD) {
        for (int i = 0; i < FD; i++) cr += sC[i] * sW[i * FD + tid];
    }
    __syncthreads();

    for (int i = tid; i < FD * FD; i += 256) sW[i] *= sA[i >> 6];
    if (tid < FD) sCrow[tid] = cr;
    __syncthreads();

    int rp = tid >> 4, tc = tid & 15;
    int rbase = rp * 4;
    float4 acc0 = make_float4(0.f, 0.f, 0.f, 0.f);
    float4 acc1 = make_float4(0.f, 0.f, 0.f, 0.f);
    float4 acc2 = make_float4(0.f, 0.f, 0.f, 0.f);
    float4 acc3 = make_float4(0.f, 0.f, 0.f, 0.f);
    const float4* sW4 = (const float4*)sW;
#pragma unroll
    for (int k = 0; k < FD; k++) {
        float4 w = sW4[k * 16 + tc];
        float x0 = sIn[(rbase + 0) * 68 + k];
        float x1 = sIn[(rbase + 1) * 68 + k];
        float x2 = sIn[(rbase + 2) * 68 + k];
        float x3 = sIn[(rbase + 3) * 68 + k];
        acc0.x += x0 * w.x; acc0.y += x0 * w.y; acc0.z += x0 * w.z; acc0.w += x0 * w.w;
        acc1.x += x1 * w.x; acc1.y += x1 * w.y; acc1.z += x1 * w.z; acc1.w += x1 * w.w;
        acc2.x += x2 * w.x; acc2.y += x2 * w.y; acc2.z += x2 * w.z; acc2.w += x2 * w.w;
        acc3.x += x3 * w.x; acc3.y += x3 * w.y; acc3.z += x3 * w.z; acc3.w += x3 * w.w;
    }
    float4 crw = ((const float4*)sCrow)[tc];
    // dinv scale per row (factored GCN norm) fused with crow add
    float d0 = (rbase + 0 < nrows) ? g_dinv[base + rbase + 0] : 0.0f;
    float d1 = (rbase + 1 < nrows) ? g_dinv[base + rbase + 1] : 0.0f;
    float d2 = (rbase + 2 < nrows) ? g_dinv[base + rbase + 2] : 0.0f;
    float d3 = (rbase + 3 < nrows) ? g_dinv[base + rbase + 3] : 0.0f;
    acc0.x = (acc0.x + crw.x) * d0; acc0.y = (acc0.y + crw.y) * d0;
    acc0.z = (acc0.z + crw.z) * d0; acc0.w = (acc0.w + crw.w) * d0;
    acc1.x = (acc1.x + crw.x) * d1; acc1.y = (acc1.y + crw.y) * d1;
    acc1.z = (acc1.z + crw.z) * d1; acc1.w = (acc1.w + crw.w) * d1;
    acc2.x = (acc2.x + crw.x) * d2; acc2.y = (acc2.y + crw.y) * d2;
    acc2.z = (acc2.z + crw.z) * d2; acc2.w = (acc2.w + crw.w) * d2;
    acc3.x = (acc3.x + crw.x) * d3; acc3.y = (acc3.y + crw.y) * d3;
    acc3.z = (acc3.z + crw.z) * d3; acc3.w = (acc3.w + crw.w) * d3;

    uint2* th2 = (uint2*)g_th;
    if (rbase + 0 < nrows) th2[(size_t)(base + rbase + 0) * 16 + tc] = make_uint2(pack_half2(acc0.x, acc0.y), pack_half2(acc0.z, acc0.w));
    if (rbase + 1 < nrows) th2[(size_t)(base + rbase + 1) * 16 + tc] = make_uint2(pack_half2(acc1.x, acc1.y), pack_half2(acc1.z, acc1.w));
    if (rbase + 2 < nrows) th2[(size_t)(base + rbase + 2) * 16 + tc] = make_uint2(pack_half2(acc2.x, acc2.y), pack_half2(acc2.z, acc2.w));
    if (rbase + 3 < nrows) th2[(size_t)(base + rbase + 3) * 16 + tc] = make_uint2(pack_half2(acc3.x, acc3.y), pack_half2(acc3.z, acc3.w));
}

// ---------------- CSR gather conv: warp/node, lane = 2 feats, fp16 messages.
//   agg[n] = dinv[n] * ( th[n] + sum_e th[src_e] )    (messages pre-scaled)
// CSR srcs read 4-at-a-time via int4 (uniform broadcast across the warp).
// Optional epilogue: BN stats of relu(agg + bias) via block reduction.
__global__ void gather_kernel(int do_stats, const float* __restrict__ bias, int soff) {
    __shared__ float sStat[128];
    int tid  = threadIdx.x;
    int lane = tid & 31;
    if (do_stats && tid < 128) sStat[tid] = 0.0f;

    int n = (blockIdx.x * blockDim.x + tid) >> 5;   // 16 nodes per 512-thread block
    const __half2* th2 = (const __half2*)g_th;
    float2 acc = __half22float2(th2[(size_t)n * 32 + lane]);  // self term (pre-scaled)

    int j = g_rowptr[n], end = g_rowptr[n + 1];
    // peel to 4-alignment
    while (j < end && (j & 3)) {
        int r = g_csr_src[j++];
        float2 v = __half22float2(th2[(size_t)r * 32 + lane]);
        acc.x += v.x; acc.y += v.y;
    }
    const int4* csr4 = (const int4*)g_csr_src;
    for (; j + 4 <= end; j += 4) {
        int4 p = csr4[j >> 2];
        float2 v0 = __half22float2(th2[(size_t)p.x * 32 + lane]);
        float2 v1 = __half22float2(th2[(size_t)p.y * 32 + lane]);
        float2 v2 = __half22float2(th2[(size_t)p.z * 32 + lane]);
        float2 v3 = __half22float2(th2[(size_t)p.w * 32 + lane]);
        acc.x += (v0.x + v1.x) + (v2.x + v3.x);
        acc.y += (v0.y + v1.y) + (v2.y + v3.y);
    }
    while (j < end) {
        int r = g_csr_src[j++];
        float2 v = __half22float2(th2[(size_t)r * 32 + lane]);
        acc.x += v.x; acc.y += v.y;
    }
    float d = g_dinv[n];
    acc.x *= d; acc.y *= d;
    ((float2*)g_agg)[(size_t)n * 32 + lane] = acc;

    if (do_stats) {
        float2 bb = ((const float2*)bias)[lane];
        float y0 = fmaxf(acc.x + bb.x, 0.0f);
        float y1 = fmaxf(acc.y + bb.y, 0.0f);
        __syncthreads();             // zero-fill visible, all accs done
        atomicAdd(&sStat[2 * lane],      y0);
        atomicAdd(&sStat[2 * lane + 1],  y1);
        atomicAdd(&sStat[64 + 2 * lane],     y0 * y0);
        atomicAdd(&sStat[64 + 2 * lane + 1], y1 * y1);
        __syncthreads();
        if (tid < 128) atomicAdd(&g_stats[soff + tid], sStat[tid]);
    }
}

// ---------------- pool: y=relu(agg+b2); BN3 stats + per-graph sums (batch sorted)
__global__ void pool_kernel(const float* __restrict__ bias, const int* __restrict__ batch) {
    int f   = threadIdx.x & 63;
    int sub = threadIdx.x >> 6;
    int is64 = g_is64;
    float bs = bias[f];
    const int chunk = 196;                 // 512 blocks * 196 >= NN
    const int subc  = 49;
    int start = blockIdx.x * chunk + sub * subc;
    int stop  = min(start + subc, NN);
    float s = 0.0f, ss = 0.0f;
    int   cur = -1;
    float gv = 0.0f, gc = 0.0f;
    for (int n = start; n < stop; n++) {
        int b = is64 ? batch[2 * n] : batch[n];
        if (b != cur) {
            if (cur >= 0) {
                atomicAdd(&g_gsum[cur * FD + f], gv);
                if (f == 0) atomicAdd(&g_gcnt[cur], gc);
            }
            cur = b; gv = 0.0f; gc = 0.0f;
        }
        float v = fmaxf(g_agg[(size_t)n * FD + f] + bs, 0.0f);
        s += v; ss += v * v;
        gv += v; gc += 1.0f;
    }
    if (cur >= 0) {
        atomicAdd(&g_gsum[cur * FD + f], gv);
        if (f == 0) atomicAdd(&g_gcnt[cur], gc);
    }
    atomicAdd(&g_stats[256 + f], s);
    atomicAdd(&g_stats[320 + f], ss);
}

// ---------------- final: fold BN3 into Wout, emit [NG, 2] --------------------
__global__ void final_kernel(const float* __restrict__ gg, const float* __restrict__ bb,
                             const float* __restrict__ Wout, const float* __restrict__ bout,
                             float* __restrict__ out) {
    __shared__ float sWp[FD * 2];
    __shared__ float sc[FD];
    __shared__ float scb[2];
    int tid = threadIdx.x;
    if (tid < FD) {
        float m = g_stats[256 + tid] * (1.0f / NN);
        float v = fmaxf(g_stats[320 + tid] * (1.0f / NN) - m * m, 0.0f);
        float af = gg[tid] * rsqrtf(v + BN_EPS);
        sc[tid] = bb[tid] - m * af;
        sWp[tid * 2]     = af * Wout[tid * 2];
        sWp[tid * 2 + 1] = af * Wout[tid * 2 + 1];
    }
    __syncthreads();
    if (tid < 2) {
        float acc = bout[tid];
        for (int i = 0; i < FD; i++) acc += sc[i] * Wout[i * 2 + tid];
        scb[tid] = acc;
    }
    __syncthreads();
    int g = blockIdx.x * blockDim.x + tid;
    if (g >= NG) return;
    float cnt = g_gcnt[g];
    if (cnt > 0.0f) {
        float inv = 1.0f / cnt;
        float a0 = scb[0], a1 = scb[1];
#pragma unroll 8
        for (int f = 0; f < FD; f++) {
            float p = g_gsum[g * FD + f] * inv;
            a0 += p * sWp[f * 2];
            a1 += p * sWp[f * 2 + 1];
        }
        out[g * 2] = a0; out[g * 2 + 1] = a1;
    } else {
        out[g * 2] = bout[0]; out[g * 2 + 1] = bout[1];
    }
}

extern "C" void kernel_launch(void* const* d_in, const int* in_sizes, int n_in,
                              void* d_out, int out_size) {
    const float* x       = (const float*)d_in[0];
    const int*   ei      = (const int*)d_in[1];
    const int*   batch   = (const int*)d_in[2];
    const float* bn_in_g = (const float*)d_in[3];
    const float* bn_in_b = (const float*)d_in[4];
    const float* W1      = (const float*)d_in[5];
    const float* b1      = (const float*)d_in[6];
    const float* g1      = (const float*)d_in[7];
    const float* be1     = (const float*)d_in[8];
    const float* W2      = (const float*)d_in[9];
    const float* b2      = (const float*)d_in[10];
    const float* g2      = (const float*)d_in[11];
    const float* be2     = (const float*)d_in[12];
    const float* Wout    = (const float*)d_in[13];
    const float* bout    = (const float*)d_in[14];
    float* out = (float*)d_out;

    const int GEMM_GRID = (NN + 63) / 64;   // 1563

    init_kernel<<<(NN + 255) / 256, 256>>>(ei);                           // 1
    deg_kernel<<<(NE / 2 + 255) / 256, 256>>>(ei);                        // 2
    scan_kernel<<<SCAN_NB, 256>>>();                                      // 3 (fused rsqrt+scan)
    place_kernel<<<(NE / 2 + 255) / 256, 256>>>(ei);                      // 4  <- profiled
    bn_stats_x_kernel<<<512, 256>>>(x);                                   // 5
    gemm_kernel<<<GEMM_GRID, 256>>>(x, 0, x, 0, bn_in_g, bn_in_b, W1, 0); // 6
    gather_kernel<<<NN / 16, 512>>>(1, b1, 128);                          // 7
    gemm_kernel<<<GEMM_GRID, 256>>>(x, 1, b1, 1, g1, be1, W2, 128);       // 8
    gather_kernel<<<NN / 16, 512>>>(0, b1, 0);                            // 9
    pool_kernel<<<512, 256>>>(b2, batch);                                 // 10
    final_kernel<<<4, 256>>>(g2, be2, Wout, bout, out);                   // 11
}

// round 12
// speedup vs baseline: 1.0843x; 1.0777x over previous
#include <cuda_runtime.h>
#include <cuda_fp16.h>

#define NN 100000
#define NE 1280000
#define FD 64
#define NG 1000
#define BN_EPS 1e-5f
#define SCAN_CH 1024
#define SCAN_NB ((NN + SCAN_CH - 1) / SCAN_CH)   // 98

// ---------------- device scratch (allocation-free rule: __device__ globals) ----
__device__ int    g_deg[NN];
__device__ float  g_dinv[NN];
__device__ __half g_th[(size_t)NN * FD];      // dinv-scaled messages (fp16)
__device__ float  g_agg[(size_t)NN * FD];     // aggregated features (fp32)
__device__ float  g_stats[6 * FD];            // s1 ss1 | s2 ss2 | s3 ss3
__device__ float  g_gsum[NG * FD];
__device__ float  g_gcnt[NG];
__device__ int    g_is64;
// CSR sorted by destination: src index only (norm factored into messages)
__device__ int    g_rowptr[NN + 1];
__device__ int    g_fill[NN];
__device__ int    g_csr_src[NE];
// decoupled-lookback scan state (reset by init each launch)
__device__ volatile int g_scan_status[SCAN_NB];   // 0=invalid 1=agg 2=prefix
__device__ volatile int g_scan_agg[SCAN_NB];
__device__ volatile int g_scan_pref[SCAN_NB];

// ---------------- second stream + fork/join events (created once, pre-main;
// no device memory allocation; identical launch pattern every call) ----------
struct HxAsync {
    cudaStream_t s;
    cudaEvent_t evInit, evBn, evScan, evPlace;
    HxAsync() {
        cudaStreamCreateWithFlags(&s, cudaStreamNonBlocking);
        cudaEventCreateWithFlags(&evInit,  cudaEventDisableTiming);
        cudaEventCreateWithFlags(&evBn,    cudaEventDisableTiming);
        cudaEventCreateWithFlags(&evScan,  cudaEventDisableTiming);
        cudaEventCreateWithFlags(&evPlace, cudaEventDisableTiming);
    }
};
static HxAsync hx;

__device__ __forceinline__ unsigned pack_half2(float a, float b) {
    __half2 h = __floats2half2_rn(a, b);
    return (unsigned)__half_as_ushort(__low2half(h)) |
           ((unsigned)__half_as_ushort(__high2half(h)) << 16);
}

// ---------------- init + dtype detect (block 0 detects int64 via odd words==0)
__global__ void init_kernel(const int* __restrict__ ei) {
    int i = blockIdx.x * blockDim.x + threadIdx.x;
    if (i < NN) g_deg[i] = 0;
    if (i < 6 * FD) g_stats[i] = 0.0f;
    if (i < NG * FD) g_gsum[i] = 0.0f;
    if (i < NG) g_gcnt[i] = 0.0f;
    if (i < SCAN_NB) g_scan_status[i] = 0;
    if (blockIdx.x == 0) {
        __shared__ int nz;
        if (threadIdx.x == 0) nz = 0;
        __syncthreads();
        int local = 0;
        for (int k = threadIdx.x; k < 4096; k += blockDim.x)
            if (ei[2 * k + 1] != 0) local = 1;
        if (local) nz = 1;
        __syncthreads();
        if (threadIdx.x == 0) g_is64 = (nz == 0) ? 1 : 0;
    }
}

// ---------------- degree: 2 edges per thread, vectorized index loads --------
__global__ void deg_kernel(const int* __restrict__ ei) {
    int e2 = blockIdx.x * blockDim.x + threadIdx.x;    // edge pair id
    if (e2 >= NE / 2) return;
    int c0, c1;
    if (g_is64) {
        int4 p = ((const int4*)(ei + 2 * NE))[e2];
        c0 = p.x; c1 = p.z;
    } else {
        int2 p = ((const int2*)(ei + NE))[e2];
        c0 = p.x; c1 = p.y;
    }
    atomicAdd(&g_deg[c0], 1);
    atomicAdd(&g_deg[c1], 1);
}

// ---------------- fused: rsqrt(deg+1) + single-pass exclusive scan ----------
__global__ void scan_kernel() {
    __shared__ int sh[257];
    __shared__ int sExc;
    int b = blockIdx.x, t = threadIdx.x;
    int base = b * SCAN_CH + t * 4;
    int v[4]; int s = 0;
#pragma unroll
    for (int k = 0; k < 4; k++) {
        int i = base + k;
        v[k] = (i < NN) ? g_deg[i] : 0;
        if (i < NN) g_dinv[i] = rsqrtf((float)v[k] + 1.0f);
        s += v[k];
    }
    sh[t + 1] = s;
    if (t == 0) sh[0] = 0;
    __syncthreads();
    for (int off = 1; off < 256; off <<= 1) {
        int val = (t + 1 > off) ? sh[t + 1 - off] : 0;
        __syncthreads();
        sh[t + 1] += val;
        __syncthreads();
    }
    int total = sh[256];

    if (t == 0) {
        if (b == 0) {
            g_scan_pref[0] = total;
            __threadfence();
            g_scan_status[0] = 2;
            sExc = 0;
        } else {
            g_scan_agg[b] = total;
            __threadfence();
            g_scan_status[b] = 1;
            int exc = 0;
            int j = b - 1;
            while (true) {
                int st;
                do { st = g_scan_status[j]; } while (st == 0);
                __threadfence();
                if (st == 2) { exc += g_scan_pref[j]; break; }
                exc += g_scan_agg[j];
                j--;
            }
            g_scan_pref[b] = exc + total;
            __threadfence();
            g_scan_status[b] = 2;
            sExc = exc;
        }
        if (b == SCAN_NB - 1) g_rowptr[NN] = g_scan_pref[b];  // == NE
    }
    __syncthreads();
    int run = sExc + sh[t];
#pragma unroll
    for (int k = 0; k < 4; k++) {
        int i = base + k;
        if (i < NN) { g_rowptr[i] = run; g_fill[i] = run; run += v[k]; }
    }
}

// ---------------- edge placement into CSR: src only (4B scattered writes) ---
__global__ void place_kernel(const int* __restrict__ ei) {
    int e2 = blockIdx.x * blockDim.x + threadIdx.x;
    if (e2 >= NE / 2) return;
    int r0, c0, r1, c1;
    if (g_is64) {
        int4 pr = ((const int4*)ei)[e2];
        int4 pc = ((const int4*)(ei + 2 * NE))[e2];
        r0 = pr.x; r1 = pr.z; c0 = pc.x; c1 = pc.z;
    } else {
        int2 pr = ((const int2*)ei)[e2];
        int2 pc = ((const int2*)(ei + NE))[e2];
        r0 = pr.x; r1 = pr.y; c0 = pc.x; c1 = pc.y;
    }
    int pos0 = atomicAdd(&g_fill[c0], 1);
    g_csr_src[pos0] = r0;
    int pos1 = atomicAdd(&g_fill[c1], 1);
    g_csr_src[pos1] = r1;
}

// ---------------- BN stats for layer-1 input x ------------------------------
__global__ void bn_stats_x_kernel(const float* __restrict__ x) {
    int f   = threadIdx.x & 63;
    int sub = threadIdx.x >> 6;
    float s = 0.0f, ss = 0.0f;
    for (int n = blockIdx.x * 4 + sub; n < NN; n += gridDim.x * 4) {
        float v = x[(size_t)n * FD + f];
        s += v; ss += v * v;
    }
    atomicAdd(&g_stats[f], s);
    atomicAdd(&g_stats[64 + f], ss);
}

// ---------------- GEMM with fused BN fold + dinv scale ----------------------
//   th = dinv[n] * ( prologue(in) @ (diag(a)W) + c@W )
// prologue = relu(in + bias) if dorelu.  Output fp16, 64 rows/block.
__global__ void gemm_kernel(const float* __restrict__ xin, int use_agg,
                            const float* __restrict__ bias, int dorelu,
                            const float* __restrict__ gg, const float* __restrict__ bb,
                            const float* __restrict__ W, int soff) {
    __shared__ float sIn[64 * 68];          // pad 68: float4-aligned rows, conflict-free
    __shared__ float sW[FD * FD];
    __shared__ float sA[FD], sC[FD], sCrow[FD];
    const float* __restrict__ src = use_agg ? g_agg : xin;
    int tid = threadIdx.x;

    for (int i = tid; i < FD * FD; i += 256) sW[i] = W[i];
    if (tid < FD) {
        float m = g_stats[soff + tid] * (1.0f / NN);
        float v = fmaxf(g_stats[soff + 64 + tid] * (1.0f / NN) - m * m, 0.0f);
        float af = gg[tid] * rsqrtf(v + BN_EPS);
        sA[tid] = af;
        sC[tid] = bb[tid] - m * af;
    }
    __syncthreads();

    int base = blockIdx.x * 64;
    int nrows = min(64, NN - base);
    for (int i = tid; i < 64 * 16; i += 256) {
        int r = i >> 4, kc = i & 15;
        float4 v = make_float4(0.f, 0.f, 0.f, 0.f);
        if (r < nrows) {
            v = ((const float4*)src)[(size_t)(base + r) * 16 + kc];
            if (dorelu) {
                float4 bv = ((const float4*)bias)[kc];
                v.x = fmaxf(v.x + bv.x, 0.0f);
                v.y = fmaxf(v.y + bv.y, 0.0f);
                v.z = fmaxf(v.z + bv.z, 0.0f);
                v.w = fmaxf(v.w + bv.w, 0.0f);
            }
        }
        *((float4*)&sIn[r * 68 + kc * 4]) = v;
    }
    float cr = 0.0f;
    if (tid < FD) {
        for (int i = 0; i < FD; i++) cr += sC[i] * sW[i * FD + tid];
    }
    __syncthreads();

    for (int i = tid; i < FD * FD; i += 256) sW[i] *= sA[i >> 6];
    if (tid < FD) sCrow[tid] = cr;
    __syncthreads();

    int rp = tid >> 4, tc = tid & 15;
    int rbase = rp * 4;
    float4 acc0 = make_float4(0.f, 0.f, 0.f, 0.f);
    float4 acc1 = make_float4(0.f, 0.f, 0.f, 0.f);
    float4 acc2 = make_float4(0.f, 0.f, 0.f, 0.f);
    float4 acc3 = make_float4(0.f, 0.f, 0.f, 0.f);
    const float4* sW4 = (const float4*)sW;
#pragma unroll
    for (int k = 0; k < FD; k++) {
        float4 w = sW4[k * 16 + tc];
        float x0 = sIn[(rbase + 0) * 68 + k];
        float x1 = sIn[(rbase + 1) * 68 + k];
        float x2 = sIn[(rbase + 2) * 68 + k];
        float x3 = sIn[(rbase + 3) * 68 + k];
        acc0.x += x0 * w.x; acc0.y += x0 * w.y; acc0.z += x0 * w.z; acc0.w += x0 * w.w;
        acc1.x += x1 * w.x; acc1.y += x1 * w.y; acc1.z += x1 * w.z; acc1.w += x1 * w.w;
        acc2.x += x2 * w.x; acc2.y += x2 * w.y; acc2.z += x2 * w.z; acc2.w += x2 * w.w;
        acc3.x += x3 * w.x; acc3.y += x3 * w.y; acc3.z += x3 * w.z; acc3.w += x3 * w.w;
    }
    float4 crw = ((const float4*)sCrow)[tc];
    float d0 = (rbase + 0 < nrows) ? g_dinv[base + rbase + 0] : 0.0f;
    float d1 = (rbase + 1 < nrows) ? g_dinv[base + rbase + 1] : 0.0f;
    float d2 = (rbase + 2 < nrows) ? g_dinv[base + rbase + 2] : 0.0f;
    float d3 = (rbase + 3 < nrows) ? g_dinv[base + rbase + 3] : 0.0f;
    acc0.x = (acc0.x + crw.x) * d0; acc0.y = (acc0.y + crw.y) * d0;
    acc0.z = (acc0.z + crw.z) * d0; acc0.w = (acc0.w + crw.w) * d0;
    acc1.x = (acc1.x + crw.x) * d1; acc1.y = (acc1.y + crw.y) * d1;
    acc1.z = (acc1.z + crw.z) * d1; acc1.w = (acc1.w + crw.w) * d1;
    acc2.x = (acc2.x + crw.x) * d2; acc2.y = (acc2.y + crw.y) * d2;
    acc2.z = (acc2.z + crw.z) * d2; acc2.w = (acc2.w + crw.w) * d2;
    acc3.x = (acc3.x + crw.x) * d3; acc3.y = (acc3.y + crw.y) * d3;
    acc3.z = (acc3.z + crw.z) * d3; acc3.w = (acc3.w + crw.w) * d3;

    uint2* th2 = (uint2*)g_th;
    if (rbase + 0 < nrows) th2[(size_t)(base + rbase + 0) * 16 + tc] = make_uint2(pack_half2(acc0.x, acc0.y), pack_half2(acc0.z, acc0.w));
    if (rbase + 1 < nrows) th2[(size_t)(base + rbase + 1) * 16 + tc] = make_uint2(pack_half2(acc1.x, acc1.y), pack_half2(acc1.z, acc1.w));
    if (rbase + 2 < nrows) th2[(size_t)(base + rbase + 2) * 16 + tc] = make_uint2(pack_half2(acc2.x, acc2.y), pack_half2(acc2.z, acc2.w));
    if (rbase + 3 < nrows) th2[(size_t)(base + rbase + 3) * 16 + tc] = make_uint2(pack_half2(acc3.x, acc3.y), pack_half2(acc3.z, acc3.w));
}

// ---------------- CSR gather conv: warp/node, lane = 2 feats, fp16 messages.
//   agg[n] = dinv[n] * ( th[n] + sum_e th[src_e] )    (messages pre-scaled)
__global__ void gather_kernel(int do_stats, const float* __restrict__ bias, int soff) {
    __shared__ float sStat[128];
    int tid  = threadIdx.x;
    int lane = tid & 31;
    if (do_stats && tid < 128) sStat[tid] = 0.0f;

    int n = (blockIdx.x * blockDim.x + tid) >> 5;   // 16 nodes per 512-thread block
    const __half2* th2 = (const __half2*)g_th;
    float2 acc = __half22float2(th2[(size_t)n * 32 + lane]);  // self term (pre-scaled)

    int j = g_rowptr[n], end = g_rowptr[n + 1];
    while (j < end && (j & 3)) {
        int r = g_csr_src[j++];
        float2 v = __half22float2(th2[(size_t)r * 32 + lane]);
        acc.x += v.x; acc.y += v.y;
    }
    const int4* csr4 = (const int4*)g_csr_src;
    for (; j + 4 <= end; j += 4) {
        int4 p = csr4[j >> 2];
        float2 v0 = __half22float2(th2[(size_t)p.x * 32 + lane]);
        float2 v1 = __half22float2(th2[(size_t)p.y * 32 + lane]);
        float2 v2 = __half22float2(th2[(size_t)p.z * 32 + lane]);
        float2 v3 = __half22float2(th2[(size_t)p.w * 32 + lane]);
        acc.x += (v0.x + v1.x) + (v2.x + v3.x);
        acc.y += (v0.y + v1.y) + (v2.y + v3.y);
    }
    while (j < end) {
        int r = g_csr_src[j++];
        float2 v = __half22float2(th2[(size_t)r * 32 + lane]);
        acc.x += v.x; acc.y += v.y;
    }
    float d = g_dinv[n];
    acc.x *= d; acc.y *= d;
    ((float2*)g_agg)[(size_t)n * 32 + lane] = acc;

    if (do_stats) {
        float2 bb = ((const float2*)bias)[lane];
        float y0 = fmaxf(acc.x + bb.x, 0.0f);
        float y1 = fmaxf(acc.y + bb.y, 0.0f);
        __syncthreads();
        atomicAdd(&sStat[2 * lane],      y0);
        atomicAdd(&sStat[2 * lane + 1],  y1);
        atomicAdd(&sStat[64 + 2 * lane],     y0 * y0);
        atomicAdd(&sStat[64 + 2 * lane + 1], y1 * y1);
        __syncthreads();
        if (tid < 128) atomicAdd(&g_stats[soff + tid], sStat[tid]);
    }
}

// ---------------- pool: y=relu(agg+b2); BN3 stats + per-graph sums (batch sorted)
__global__ void pool_kernel(const float* __restrict__ bias, const int* __restrict__ batch) {
    int f   = threadIdx.x & 63;
    int sub = threadIdx.x >> 6;
    int is64 = g_is64;
    float bs = bias[f];
    const int chunk = 196;
    const int subc  = 49;
    int start = blockIdx.x * chunk + sub * subc;
    int stop  = min(start + subc, NN);
    float s = 0.0f, ss = 0.0f;
    int   cur = -1;
    float gv = 0.0f, gc = 0.0f;
    for (int n = start; n < stop; n++) {
        int b = is64 ? batch[2 * n] : batch[n];
        if (b != cur) {
            if (cur >= 0) {
                atomicAdd(&g_gsum[cur * FD + f], gv);
                if (f == 0) atomicAdd(&g_gcnt[cur], gc);
            }
            cur = b; gv = 0.0f; gc = 0.0f;
        }
        float v = fmaxf(g_agg[(size_t)n * FD + f] + bs, 0.0f);
        s += v; ss += v * v;
        gv += v; gc += 1.0f;
    }
    if (cur >= 0) {
        atomicAdd(&g_gsum[cur * FD + f], gv);
        if (f == 0) atomicAdd(&g_gcnt[cur], gc);
    }
    atomicAdd(&g_stats[256 + f], s);
    atomicAdd(&g_stats[320 + f], ss);
}

// ---------------- final: fold BN3 into Wout, emit [NG, 2] --------------------
__global__ void final_kernel(const float* __restrict__ gg, const float* __restrict__ bb,
                             const float* __restrict__ Wout, const float* __restrict__ bout,
                             float* __restrict__ out) {
    __shared__ float sWp[FD * 2];
    __shared__ float sc[FD];
    __shared__ float scb[2];
    int tid = threadIdx.x;
    if (tid < FD) {
        float m = g_stats[256 + tid] * (1.0f / NN);
        float v = fmaxf(g_stats[320 + tid] * (1.0f / NN) - m * m, 0.0f);
        float af = gg[tid] * rsqrtf(v + BN_EPS);
        sc[tid] = bb[tid] - m * af;
        sWp[tid * 2]     = af * Wout[tid * 2];
        sWp[tid * 2 + 1] = af * Wout[tid * 2 + 1];
    }
    __syncthreads();
    if (tid < 2) {
        float acc = bout[tid];
        for (int i = 0; i < FD; i++) acc += sc[i] * Wout[i * 2 + tid];
        scb[tid] = acc;
    }
    __syncthreads();
    int g = blockIdx.x * blockDim.x + tid;
    if (g >= NG) return;
    float cnt = g_gcnt[g];
    if (cnt > 0.0f) {
        float inv = 1.0f / cnt;
        float a0 = scb[0], a1 = scb[1];
#pragma unroll 8
        for (int f = 0; f < FD; f++) {
            float p = g_gsum[g * FD + f] * inv;
            a0 += p * sWp[f * 2];
            a1 += p * sWp[f * 2 + 1];
        }
        out[g * 2] = a0; out[g * 2 + 1] = a1;
    } else {
        out[g * 2] = bout[0]; out[g * 2 + 1] = bout[1];
    }
}

extern "C" void kernel_launch(void* const* d_in, const int* in_sizes, int n_in,
                              void* d_out, int out_size) {
    const float* x       = (const float*)d_in[0];
    const int*   ei      = (const int*)d_in[1];
    const int*   batch   = (const int*)d_in[2];
    const float* bn_in_g = (const float*)d_in[3];
    const float* bn_in_b = (const float*)d_in[4];
    const float* W1      = (const float*)d_in[5];
    const float* b1      = (const float*)d_in[6];
    const float* g1      = (const float*)d_in[7];
    const float* be1     = (const float*)d_in[8];
    const float* W2      = (const float*)d_in[9];
    const float* b2      = (const float*)d_in[10];
    const float* g2      = (const float*)d_in[11];
    const float* be2     = (const float*)d_in[12];
    const float* Wout    = (const float*)d_in[13];
    const float* bout    = (const float*)d_in[14];
    float* out = (float*)d_out;

    const int GEMM_GRID = (NN + 63) / 64;   // 1563

    // stream 0:  init -> deg -> scan ------------------\-> gemm1 ----------> gather1 -> gemm2 -> gather2 -> pool -> final
    // stream B:  (after init) bn_stats_x --(after scan)-> place --(join)----^
    init_kernel<<<(NN + 255) / 256, 256>>>(ei);
    cudaEventRecord(hx.evInit, 0);
    cudaStreamWaitEvent(hx.s, hx.evInit, 0);
    bn_stats_x_kernel<<<512, 256, 0, hx.s>>>(x);                  // ∥ deg+scan
    cudaEventRecord(hx.evBn, hx.s);

    deg_kernel<<<(NE / 2 + 255) / 256, 256>>>(ei);
    scan_kernel<<<SCAN_NB, 256>>>();
    cudaEventRecord(hx.evScan, 0);

    cudaStreamWaitEvent(hx.s, hx.evScan, 0);
    place_kernel<<<(NE / 2 + 255) / 256, 256, 0, hx.s>>>(ei);     // ∥ gemm1
    cudaEventRecord(hx.evPlace, hx.s);

    cudaStreamWaitEvent(0, hx.evBn, 0);                           // stats ready
    gemm_kernel<<<GEMM_GRID, 256>>>(x, 0, x, 0, bn_in_g, bn_in_b, W1, 0);

    cudaStreamWaitEvent(0, hx.evPlace, 0);                        // CSR ready
    gather_kernel<<<NN / 16, 512>>>(1, b1, 128);                  // conv1 agg + BN2 stats
    gemm_kernel<<<GEMM_GRID, 256>>>(x, 1, b1, 1, g1, be1, W2, 128);
    gather_kernel<<<NN / 16, 512>>>(0, b1, 0);                    // conv2 agg
    pool_kernel<<<512, 256>>>(b2, batch);
    final_kernel<<<4, 256>>>(g2, be2, Wout, bout, out);
}

// round 13
// speedup vs baseline: 1.1299x; 1.0421x over previous
#include <cuda_runtime.h>
#include <cuda_fp16.h>

#define NN 100000
#define NE 1280000
#define FD 64
#define NG 1000
#define BN_EPS 1e-5f
#define SCAN_CH 2048
#define SCAN_NB ((NN + SCAN_CH - 1) / SCAN_CH)   // 49

// ---------------- device scratch (allocation-free rule: __device__ globals) ----
__device__ int    g_deg[NN];
__device__ float  g_dinv[NN];
__device__ __half g_th[(size_t)NN * FD];      // dinv-scaled messages (fp16)
__device__ float  g_agg[(size_t)NN * FD];     // aggregated features (fp32)
__device__ float  g_stats[6 * FD];            // s1 ss1 | s2 ss2 | s3 ss3
__device__ float  g_gsum[NG * FD];
__device__ float  g_gcnt[NG];
__device__ int    g_is64;
// CSR sorted by destination: src index only (norm factored into messages)
__device__ int    g_rowptr[NN + 1];
__device__ int    g_fill[NN];
__device__ int    g_csr_src[NE];
// decoupled-lookback scan state (reset by init each launch)
__device__ volatile int g_scan_status[SCAN_NB];   // 0=invalid 1=agg 2=prefix
__device__ volatile int g_scan_agg[SCAN_NB];
__device__ volatile int g_scan_pref[SCAN_NB];

// ---------------- second stream + fork/join events (created once, pre-main) --
struct HxAsync {
    cudaStream_t s;
    cudaEvent_t evInit, evBn, evScan, evPlace;
    HxAsync() {
        cudaStreamCreateWithFlags(&s, cudaStreamNonBlocking);
        cudaEventCreateWithFlags(&evInit,  cudaEventDisableTiming);
        cudaEventCreateWithFlags(&evBn,    cudaEventDisableTiming);
        cudaEventCreateWithFlags(&evScan,  cudaEventDisableTiming);
        cudaEventCreateWithFlags(&evPlace, cudaEventDisableTiming);
    }
};
static HxAsync hx;

__device__ __forceinline__ unsigned pack_half2(float a, float b) {
    __half2 h = __floats2half2_rn(a, b);
    return (unsigned)__half_as_ushort(__low2half(h)) |
           ((unsigned)__half_as_ushort(__high2half(h)) << 16);
}

// ---------------- init + dtype detect (block 0 detects int64 via odd words==0)
__global__ void init_kernel(const int* __restrict__ ei) {
    int i = blockIdx.x * blockDim.x + threadIdx.x;
    if (i < NN) g_deg[i] = 0;
    if (i < 6 * FD) g_stats[i] = 0.0f;
    if (i < NG * FD) g_gsum[i] = 0.0f;
    if (i < NG) g_gcnt[i] = 0.0f;
    if (i < SCAN_NB) g_scan_status[i] = 0;
    if (blockIdx.x == 0) {
        __shared__ int nz;
        if (threadIdx.x == 0) nz = 0;
        __syncthreads();
        int local = 0;
        for (int k = threadIdx.x; k < 4096; k += blockDim.x)
            if (ei[2 * k + 1] != 0) local = 1;
        if (local) nz = 1;
        __syncthreads();
        if (threadIdx.x == 0) g_is64 = (nz == 0) ? 1 : 0;
    }
}

// ---------------- degree: 2 edges per thread, vectorized index loads --------
__global__ void deg_kernel(const int* __restrict__ ei) {
    int e2 = blockIdx.x * blockDim.x + threadIdx.x;    // edge pair id
    if (e2 >= NE / 2) return;
    int c0, c1;
    if (g_is64) {
        int4 p = ((const int4*)(ei + 2 * NE))[e2];
        c0 = p.x; c1 = p.z;
    } else {
        int2 p = ((const int2*)(ei + NE))[e2];
        c0 = p.x; c1 = p.y;
    }
    atomicAdd(&g_deg[c0], 1);
    atomicAdd(&g_deg[c1], 1);
}

// ---------------- fused: rsqrt(deg+1) + single-pass exclusive scan ----------
// Decoupled lookback with WARP-PARALLEL window (32 predecessors per round).
__global__ void scan_kernel() {
    __shared__ int sh[257];
    __shared__ int sExc;
    int b = blockIdx.x, t = threadIdx.x;
    int base = b * SCAN_CH + t * 8;
    int v[8]; int s = 0;
#pragma unroll
    for (int k = 0; k < 8; k++) {
        int i = base + k;
        v[k] = (i < NN) ? g_deg[i] : 0;
        if (i < NN) g_dinv[i] = rsqrtf((float)v[k] + 1.0f);
        s += v[k];
    }
    sh[t + 1] = s;
    if (t == 0) sh[0] = 0;
    __syncthreads();
    for (int off = 1; off < 256; off <<= 1) {
        int val = (t + 1 > off) ? sh[t + 1 - off] : 0;
        __syncthreads();
        sh[t + 1] += val;
        __syncthreads();
    }
    int total = sh[256];

    // publish aggregate first (all blocks), then lookback with warp 0
    if (t == 0) {
        if (b == 0) {
            g_scan_pref[0] = total;
            __threadfence();
            g_scan_status[0] = 2;
            sExc = 0;
        } else {
            g_scan_agg[b] = total;
            __threadfence();
            g_scan_status[b] = 1;
        }
    }
    __syncthreads();
    if (b > 0 && t < 32) {
        int lane = t;
        int exc = 0;
        int lb = b - 1;
        while (true) {
            int idx = lb - lane;
            int st = 0, val = 0;
            if (idx >= 0) {
                do { st = g_scan_status[idx]; } while (st == 0);
                __threadfence();
                val = (st == 2) ? g_scan_pref[idx] : g_scan_agg[idx];
            }
            unsigned pmask = __ballot_sync(0xffffffffu, idx >= 0 && st == 2);
            int contrib;
            if (pmask) {
                int fp = __ffs(pmask) - 1;           // nearest predecessor with prefix
                contrib = (lane <= fp && idx >= 0) ? val : 0;
            } else {
                contrib = (idx >= 0) ? val : 0;
            }
#pragma unroll
            for (int o = 16; o > 0; o >>= 1)
                contrib += __shfl_down_sync(0xffffffffu, contrib, o);
            contrib = __shfl_sync(0xffffffffu, contrib, 0);
            exc += contrib;
            if (pmask) break;
            lb -= 32;
            if (lb < 0) break;                       // safety (can't happen: block 0 has prefix)
        }
        if (lane == 0) {
            g_scan_pref[b] = exc + total;
            __threadfence();
            g_scan_status[b] = 2;
            sExc = exc;
        }
    }
    __syncthreads();
    int run = sExc + sh[t];
#pragma unroll
    for (int k = 0; k < 8; k++) {
        int i = base + k;
        if (i < NN) { g_rowptr[i] = run; g_fill[i] = run; run += v[k]; }
    }
    if (b == SCAN_NB - 1 && t == 255) {
        // last element of last block: rowptr[NN] = total edges
        // (sExc + sh[256] == NE)
        g_rowptr[NN] = sExc + sh[256];
    }
}

// ---------------- edge placement into CSR: src only (4B scattered writes) ---
__global__ void place_kernel(const int* __restrict__ ei) {
    int e2 = blockIdx.x * blockDim.x + threadIdx.x;
    if (e2 >= NE / 2) return;
    int r0, c0, r1, c1;
    if (g_is64) {
        int4 pr = ((const int4*)ei)[e2];
        int4 pc = ((const int4*)(ei + 2 * NE))[e2];
        r0 = pr.x; r1 = pr.z; c0 = pc.x; c1 = pc.z;
    } else {
        int2 pr = ((const int2*)ei)[e2];
        int2 pc = ((const int2*)(ei + NE))[e2];
        r0 = pr.x; r1 = pr.y; c0 = pc.x; c1 = pc.y;
    }
    int pos0 = atomicAdd(&g_fill[c0], 1);
    g_csr_src[pos0] = r0;
    int pos1 = atomicAdd(&g_fill[c1], 1);
    g_csr_src[pos1] = r1;
}

// ---------------- BN stats for layer-1 input x ------------------------------
__global__ void bn_stats_x_kernel(const float* __restrict__ x) {
    int f   = threadIdx.x & 63;
    int sub = threadIdx.x >> 6;
    float s = 0.0f, ss = 0.0f;
    for (int n = blockIdx.x * 4 + sub; n < NN; n += gridDim.x * 4) {
        float v = x[(size_t)n * FD + f];
        s += v; ss += v * v;
    }
    atomicAdd(&g_stats[f], s);
    atomicAdd(&g_stats[64 + f], ss);
}

// ---------------- GEMM with fused BN fold + dinv scale ----------------------
//   th = dinv[n] * ( prologue(in) @ (diag(a)W) + c@W )
__global__ void gemm_kernel(const float* __restrict__ xin, int use_agg,
                            const float* __restrict__ bias, int dorelu,
                            const float* __restrict__ gg, const float* __restrict__ bb,
                            const float* __restrict__ W, int soff) {
    __shared__ float sIn[64 * 68];
    __shared__ float sW[FD * FD];
    __shared__ float sA[FD], sC[FD], sCrow[FD];
    const float* __restrict__ src = use_agg ? g_agg : xin;
    int tid = threadIdx.x;

    for (int i = tid; i < FD * FD; i += 256) sW[i] = W[i];
    if (tid < FD) {
        float m = g_stats[soff + tid] * (1.0f / NN);
        float v = fmaxf(g_stats[soff + 64 + tid] * (1.0f / NN) - m * m, 0.0f);
        float af = gg[tid] * rsqrtf(v + BN_EPS);
        sA[tid] = af;
        sC[tid] = bb[tid] - m * af;
    }
    __syncthreads();

    int base = blockIdx.x * 64;
    int nrows = min(64, NN - base);
    for (int i = tid; i < 64 * 16; i += 256) {
        int r = i >> 4, kc = i & 15;
        float4 v = make_float4(0.f, 0.f, 0.f, 0.f);
        if (r < nrows) {
            v = ((const float4*)src)[(size_t)(base + r) * 16 + kc];
            if (dorelu) {
                float4 bv = ((const float4*)bias)[kc];
                v.x = fmaxf(v.x + bv.x, 0.0f);
                v.y = fmaxf(v.y + bv.y, 0.0f);
                v.z = fmaxf(v.z + bv.z, 0.0f);
                v.w = fmaxf(v.w + bv.w, 0.0f);
            }
        }
        *((float4*)&sIn[r * 68 + kc * 4]) = v;
    }
    float cr = 0.0f;
    if (tid < FD) {
        for (int i = 0; i < FD; i++) cr += sC[i] * sW[i * FD + tid];
    }
    __syncthreads();

    for (int i = tid; i < FD * FD; i += 256) sW[i] *= sA[i >> 6];
    if (tid < FD) sCrow[tid] = cr;
    __syncthreads();

    int rp = tid >> 4, tc = tid & 15;
    int rbase = rp * 4;
    float4 acc0 = make_float4(0.f, 0.f, 0.f, 0.f);
    float4 acc1 = make_float4(0.f, 0.f, 0.f, 0.f);
    float4 acc2 = make_float4(0.f, 0.f, 0.f, 0.f);
    float4 acc3 = make_float4(0.f, 0.f, 0.f, 0.f);
    const float4* sW4 = (const float4*)sW;
#pragma unroll
    for (int k = 0; k < FD; k++) {
        float4 w = sW4[k * 16 + tc];
        float x0 = sIn[(rbase + 0) * 68 + k];
        float x1 = sIn[(rbase + 1) * 68 + k];
        float x2 = sIn[(rbase + 2) * 68 + k];
        float x3 = sIn[(rbase + 3) * 68 + k];
        acc0.x += x0 * w.x; acc0.y += x0 * w.y; acc0.z += x0 * w.z; acc0.w += x0 * w.w;
        acc1.x += x1 * w.x; acc1.y += x1 * w.y; acc1.z += x1 * w.z; acc1.w += x1 * w.w;
        acc2.x += x2 * w.x; acc2.y += x2 * w.y; acc2.z += x2 * w.z; acc2.w += x2 * w.w;
        acc3.x += x3 * w.x; acc3.y += x3 * w.y; acc3.z += x3 * w.z; acc3.w += x3 * w.w;
    }
    float4 crw = ((const float4*)sCrow)[tc];
    float d0 = (rbase + 0 < nrows) ? g_dinv[base + rbase + 0] : 0.0f;
    float d1 = (rbase + 1 < nrows) ? g_dinv[base + rbase + 1] : 0.0f;
    float d2 = (rbase + 2 < nrows) ? g_dinv[base + rbase + 2] : 0.0f;
    float d3 = (rbase + 3 < nrows) ? g_dinv[base + rbase + 3] : 0.0f;
    acc0.x = (acc0.x + crw.x) * d0; acc0.y = (acc0.y + crw.y) * d0;
    acc0.z = (acc0.z + crw.z) * d0; acc0.w = (acc0.w + crw.w) * d0;
    acc1.x = (acc1.x + crw.x) * d1; acc1.y = (acc1.y + crw.y) * d1;
    acc1.z = (acc1.z + crw.z) * d1; acc1.w = (acc1.w + crw.w) * d1;
    acc2.x = (acc2.x + crw.x) * d2; acc2.y = (acc2.y + crw.y) * d2;
    acc2.z = (acc2.z + crw.z) * d2; acc2.w = (acc2.w + crw.w) * d2;
    acc3.x = (acc3.x + crw.x) * d3; acc3.y = (acc3.y + crw.y) * d3;
    acc3.z = (acc3.z + crw.z) * d3; acc3.w = (acc3.w + crw.w) * d3;

    uint2* th2 = (uint2*)g_th;
    if (rbase + 0 < nrows) th2[(size_t)(base + rbase + 0) * 16 + tc] = make_uint2(pack_half2(acc0.x, acc0.y), pack_half2(acc0.z, acc0.w));
    if (rbase + 1 < nrows) th2[(size_t)(base + rbase + 1) * 16 + tc] = make_uint2(pack_half2(acc1.x, acc1.y), pack_half2(acc1.z, acc1.w));
    if (rbase + 2 < nrows) th2[(size_t)(base + rbase + 2) * 16 + tc] = make_uint2(pack_half2(acc2.x, acc2.y), pack_half2(acc2.z, acc2.w));
    if (rbase + 3 < nrows) th2[(size_t)(base + rbase + 3) * 16 + tc] = make_uint2(pack_half2(acc3.x, acc3.y), pack_half2(acc3.z, acc3.w));
}

// ---------------- CSR gather conv: warp/node, lane = 2 feats, fp16 messages.
//   agg[n] = dinv[n] * ( th[n] + sum_e th[src_e] )    (messages pre-scaled)
__global__ void gather_kernel(int do_stats, const float* __restrict__ bias, int soff) {
    __shared__ float sStat[128];
    int tid  = threadIdx.x;
    int lane = tid & 31;
    if (do_stats && tid < 128) sStat[tid] = 0.0f;

    int n = (blockIdx.x * blockDim.x + tid) >> 5;   // 16 nodes per 512-thread block
    const __half2* th2 = (const __half2*)g_th;
    float2 acc = __half22float2(th2[(size_t)n * 32 + lane]);  // self term (pre-scaled)

    int j = g_rowptr[n], end = g_rowptr[n + 1];
    while (j < end && (j & 3)) {
        int r = g_csr_src[j++];
        float2 v = __half22float2(th2[(size_t)r * 32 + lane]);
        acc.x += v.x; acc.y += v.y;
    }
    const int4* csr4 = (const int4*)g_csr_src;
    for (; j + 4 <= end; j += 4) {
        int4 p = csr4[j >> 2];
        float2 v0 = __half22float2(th2[(size_t)p.x * 32 + lane]);
        float2 v1 = __half22float2(th2[(size_t)p.y * 32 + lane]);
        float2 v2 = __half22float2(th2[(size_t)p.z * 32 + lane]);
        float2 v3 = __half22float2(th2[(size_t)p.w * 32 + lane]);
        acc.x += (v0.x + v1.x) + (v2.x + v3.x);
        acc.y += (v0.y + v1.y) + (v2.y + v3.y);
    }
    while (j < end) {
        int r = g_csr_src[j++];
        float2 v = __half22float2(th2[(size_t)r * 32 + lane]);
        acc.x += v.x; acc.y += v.y;
    }
    float d = g_dinv[n];
    acc.x *= d; acc.y *= d;
    ((float2*)g_agg)[(size_t)n * 32 + lane] = acc;

    if (do_stats) {
        float2 bb = ((const float2*)bias)[lane];
        float y0 = fmaxf(acc.x + bb.x, 0.0f);
        float y1 = fmaxf(acc.y + bb.y, 0.0f);
        __syncthreads();
        atomicAdd(&sStat[2 * lane],      y0);
        atomicAdd(&sStat[2 * lane + 1],  y1);
        atomicAdd(&sStat[64 + 2 * lane],     y0 * y0);
        atomicAdd(&sStat[64 + 2 * lane + 1], y1 * y1);
        __syncthreads();
        if (tid < 128) atomicAdd(&g_stats[soff + tid], sStat[tid]);
    }
}

// ---------------- pool: y=relu(agg+b2); BN3 stats + per-graph sums (batch sorted)
__global__ void pool_kernel(const float* __restrict__ bias, const int* __restrict__ batch) {
    int f   = threadIdx.x & 63;
    int sub = threadIdx.x >> 6;
    int is64 = g_is64;
    float bs = bias[f];
    const int chunk = 196;
    const int subc  = 49;
    int start = blockIdx.x * chunk + sub * subc;
    int stop  = min(start + subc, NN);
    float s = 0.0f, ss = 0.0f;
    int   cur = -1;
    float gv = 0.0f, gc = 0.0f;
    for (int n = start; n < stop; n++) {
        int b = is64 ? batch[2 * n] : batch[n];
        if (b != cur) {
            if (cur >= 0) {
                atomicAdd(&g_gsum[cur * FD + f], gv);
                if (f == 0) atomicAdd(&g_gcnt[cur], gc);
            }
            cur = b; gv = 0.0f; gc = 0.0f;
        }
        float v = fmaxf(g_agg[(size_t)n * FD + f] + bs, 0.0f);
        s += v; ss += v * v;
        gv += v; gc += 1.0f;
    }
    if (cur >= 0) {
        atomicAdd(&g_gsum[cur * FD + f], gv);
        if (f == 0) atomicAdd(&g_gcnt[cur], gc);
    }
    atomicAdd(&g_stats[256 + f], s);
    atomicAdd(&g_stats[320 + f], ss);
}

// ---------------- final: fold BN3 into Wout, emit [NG, 2] --------------------
__global__ void final_kernel(const float* __restrict__ gg, const float* __restrict__ bb,
                             const float* __restrict__ Wout, const float* __restrict__ bout,
                             float* __restrict__ out) {
    __shared__ float sWp[FD * 2];
    __shared__ float sc[FD];
    __shared__ float scb[2];
    int tid = threadIdx.x;
    if (tid < FD) {
        float m = g_stats[256 + tid] * (1.0f / NN);
        float v = fmaxf(g_stats[320 + tid] * (1.0f / NN) - m * m, 0.0f);
        float af = gg[tid] * rsqrtf(v + BN_EPS);
        sc[tid] = bb[tid] - m * af;
        sWp[tid * 2]     = af * Wout[tid * 2];
        sWp[tid * 2 + 1] = af * Wout[tid * 2 + 1];
    }
    __syncthreads();
    if (tid < 2) {
        float acc = bout[tid];
        for (int i = 0; i < FD; i++) acc += sc[i] * Wout[i * 2 + tid];
        scb[tid] = acc;
    }
    __syncthreads();
    int g = blockIdx.x * blockDim.x + tid;
    if (g >= NG) return;
    float cnt = g_gcnt[g];
    if (cnt > 0.0f) {
        float inv = 1.0f / cnt;
        float a0 = scb[0], a1 = scb[1];
#pragma unroll 8
        for (int f = 0; f < FD; f++) {
            float p = g_gsum[g * FD + f] * inv;
            a0 += p * sWp[f * 2];
            a1 += p * sWp[f * 2 + 1];
        }
        out[g * 2] = a0; out[g * 2 + 1] = a1;
    } else {
        out[g * 2] = bout[0]; out[g * 2 + 1] = bout[1];
    }
}

extern "C" void kernel_launch(void* const* d_in, const int* in_sizes, int n_in,
                              void* d_out, int out_size) {
    const float* x       = (const float*)d_in[0];
    const int*   ei      = (const int*)d_in[1];
    const int*   batch   = (const int*)d_in[2];
    const float* bn_in_g = (const float*)d_in[3];
    const float* bn_in_b = (const float*)d_in[4];
    const float* W1      = (const float*)d_in[5];
    const float* b1      = (const float*)d_in[6];
    const float* g1      = (const float*)d_in[7];
    const float* be1     = (const float*)d_in[8];
    const float* W2      = (const float*)d_in[9];
    const float* b2      = (const float*)d_in[10];
    const float* g2      = (const float*)d_in[11];
    const float* be2     = (const float*)d_in[12];
    const float* Wout    = (const float*)d_in[13];
    const float* bout    = (const float*)d_in[14];
    float* out = (float*)d_out;

    const int GEMM_GRID = (NN + 63) / 64;   // 1563

    // stream 0:  init -> deg -> scan ------------------\-> gemm1 ----------> gather1 -> gemm2 -> gather2 -> pool -> final
    // stream B:  (after init) bn_stats_x --(after scan)-> place --(join)----^
    init_kernel<<<(NN + 255) / 256, 256>>>(ei);
    cudaEventRecord(hx.evInit, 0);
    cudaStreamWaitEvent(hx.s, hx.evInit, 0);
    bn_stats_x_kernel<<<512, 256, 0, hx.s>>>(x);                  // ∥ deg+scan
    cudaEventRecord(hx.evBn, hx.s);

    deg_kernel<<<(NE / 2 + 255) / 256, 256>>>(ei);
    scan_kernel<<<SCAN_NB, 256>>>();
    cudaEventRecord(hx.evScan, 0);

    cudaStreamWaitEvent(hx.s, hx.evScan, 0);
    place_kernel<<<(NE / 2 + 255) / 256, 256, 0, hx.s>>>(ei);     // ∥ gemm1
    cudaEventRecord(hx.evPlace, hx.s);

    cudaStreamWaitEvent(0, hx.evBn, 0);                           // stats ready
    gemm_kernel<<<GEMM_GRID, 256>>>(x, 0, x, 0, bn_in_g, bn_in_b, W1, 0);

    cudaStreamWaitEvent(0, hx.evPlace, 0);                        // CSR ready
    gather_kernel<<<NN / 16, 512>>>(1, b1, 128);                  // conv1 agg + BN2 stats
    gemm_kernel<<<GEMM_GRID, 256>>>(x, 1, b1, 1, g1, be1, W2, 128);
    gather_kernel<<<NN / 16, 512>>>(0, b1, 0);                    // conv2 agg
    pool_kernel<<<512, 256>>>(b2, batch);
    final_kernel<<<4, 256>>>(g2, be2, Wout, bout, out);
}